// round 6
// baseline (speedup 1.0000x reference)
#include <cuda_runtime.h>
#include <cuda_bf16.h>
#include <cuda_fp16.h>
#include <cstdint>

#define NN    100000
#define EE    1600000
#define INC   256
#define OUTC  128

// ------------------------- device scratch -------------------------
__device__ __half        g_Hh[(size_t)NN * OUTC];    // H = X @ W^T (fp16)
__device__ int           g_row_ptr[NN + 1];
__device__ __nv_bfloat16 g_Whi[OUTC * INC];
__device__ __nv_bfloat16 g_Wlo[OUTC * INC];

// ------------------------- helpers -------------------------
__device__ __forceinline__ uint32_t smem_u32(const void* p) {
    uint32_t a;
    asm("{ .reg .u64 t; cvta.to.shared.u64 t, %1; cvt.u32.u64 %0, t; }"
        : "=r"(a) : "l"(p));
    return a;
}

__device__ __forceinline__ void ldm_x4(uint32_t* r, uint32_t addr) {
    asm volatile("ldmatrix.sync.aligned.m8n8.x4.shared.b16 {%0,%1,%2,%3}, [%4];"
                 : "=r"(r[0]), "=r"(r[1]), "=r"(r[2]), "=r"(r[3]) : "r"(addr));
}
__device__ __forceinline__ void ldm_x2(uint32_t* r, uint32_t addr) {
    asm volatile("ldmatrix.sync.aligned.m8n8.x2.shared.b16 {%0,%1}, [%2];"
                 : "=r"(r[0]), "=r"(r[1]) : "r"(addr));
}
__device__ __forceinline__ void mma_bf16(float* c, const uint32_t* a, const uint32_t* b) {
    asm volatile(
        "mma.sync.aligned.m16n8k16.row.col.f32.bf16.bf16.f32 "
        "{%0,%1,%2,%3}, {%4,%5,%6,%7}, {%8,%9}, {%0,%1,%2,%3};"
        : "+f"(c[0]), "+f"(c[1]), "+f"(c[2]), "+f"(c[3])
        : "r"(a[0]), "r"(a[1]), "r"(a[2]), "r"(a[3]), "r"(b[0]), "r"(b[1]));
}

// ------------------------- Kernel 0: split W into bf16 hi/lo -------------------------
__global__ void wconv_kernel(const float* __restrict__ W) {
    int i = blockIdx.x * blockDim.x + threadIdx.x;
    if (i < OUTC * INC) {
        float w = W[i];
        __nv_bfloat16 h = __float2bfloat16(w);
        float r = w - __bfloat162float(h);
        g_Whi[i] = h;
        g_Wlo[i] = __float2bfloat16(r);
    }
}

// ------------------------- Kernel 1: mma.sync bf16 split GEMM -------------------------
// H[m][n] = sum_k X[m][k] * W[n][k].  CTA tile 128x128, K-tiles of 64.
// 8 warps: warp_m = wid%4 (32 rows), warp_n = wid/4 (64 cols).
// 3 products per fragment: hi*hi + hi*lo + lo*hi.
//
// SMEM (halves, row stride 72 = 144B for 16B-aligned, conflict-free ldmatrix):
//   A_hi[128][72], A_lo[128][72], B_hi[128][72], B_lo[128][72]
#define LDH 72
#define SM_AHI 0
#define SM_ALO (128 * LDH)
#define SM_BHI (2 * 128 * LDH)
#define SM_BLO (3 * 128 * LDH)
#define SM_HALVES (4 * 128 * LDH)
#define SM_BYTES (SM_HALVES * 2)   // 73728

__global__ __launch_bounds__(256, 2)
void gemm_tc_kernel(const float* __restrict__ X)
{
    extern __shared__ __half sm[];
    const uint32_t sb = smem_u32(sm);

    const int tid = threadIdx.x;
    const int wid = tid >> 5;
    const int lane = tid & 31;
    const int block_row = blockIdx.x * 128;

    const int wm = (wid & 3) * 32;   // warp row offset in tile
    const int wn = (wid >> 2) * 64;  // warp col offset in tile

    float c[2][8][4];
#pragma unroll
    for (int mi = 0; mi < 2; mi++)
#pragma unroll
        for (int ni = 0; ni < 8; ni++)
#pragma unroll
            for (int j = 0; j < 4; j++)
                c[mi][ni][j] = 0.0f;

    // ldmatrix lane addressing (precomputed row/col pieces)
    const int a_row = (lane & 7) + 8 * ((lane >> 3) & 1);  // 0..15
    const int a_kh  = 8 * (lane >> 4);                     // 0 or 8
    const int l2    = lane & 15;
    const int b_row = l2 & 7;
    const int b_kh  = 8 * (l2 >> 3);

#pragma unroll 1
    for (int kt = 0; kt < 4; kt++) {
        const int k0 = kt * 64;
        if (kt) __syncthreads();

        // --- X tile: 128 rows x 64 floats -> bf16 hi/lo ---
#pragma unroll
        for (int i = 0; i < 8; i++) {
            int slot = i * 256 + tid;          // 0..2047 float4 slots
            int row  = slot >> 4;
            int kq   = (slot & 15) << 2;
            int gm   = block_row + row;
            float4 v = make_float4(0.f, 0.f, 0.f, 0.f);
            if (gm < NN)
                v = *reinterpret_cast<const float4*>(X + (size_t)gm * INC + k0 + kq);
            __nv_bfloat16 h0 = __float2bfloat16(v.x);
            __nv_bfloat16 h1 = __float2bfloat16(v.y);
            __nv_bfloat16 h2 = __float2bfloat16(v.z);
            __nv_bfloat16 h3 = __float2bfloat16(v.w);
            __nv_bfloat162 hp0(h0, h1), hp1(h2, h3);
            __nv_bfloat162 lp0(__float2bfloat16(v.x - __bfloat162float(h0)),
                               __float2bfloat16(v.y - __bfloat162float(h1)));
            __nv_bfloat162 lp1(__float2bfloat16(v.z - __bfloat162float(h2)),
                               __float2bfloat16(v.w - __bfloat162float(h3)));
            uint2 hw, lw;
            hw.x = *reinterpret_cast<uint32_t*>(&hp0);
            hw.y = *reinterpret_cast<uint32_t*>(&hp1);
            lw.x = *reinterpret_cast<uint32_t*>(&lp0);
            lw.y = *reinterpret_cast<uint32_t*>(&lp1);
            int off = row * LDH + kq;
            *reinterpret_cast<uint2*>(&sm[SM_AHI + off]) = hw;
            *reinterpret_cast<uint2*>(&sm[SM_ALO + off]) = lw;
        }
        // --- W tile: 128 n x 64 halves (preconverted bf16) ---
#pragma unroll
        for (int i = 0; i < 4; i++) {
            int slot = i * 256 + tid;          // 0..1023 uint4 slots
            int n    = slot >> 3;
            int kc   = (slot & 7) << 3;
            int off  = n * LDH + kc;
            *reinterpret_cast<uint4*>(&sm[SM_BHI + off]) =
                *reinterpret_cast<const uint4*>(g_Whi + n * INC + k0 + kc);
            *reinterpret_cast<uint4*>(&sm[SM_BLO + off]) =
                *reinterpret_cast<const uint4*>(g_Wlo + n * INC + k0 + kc);
        }
        __syncthreads();

        // --- compute: 4 k16 steps ---
#pragma unroll
        for (int ks = 0; ks < 4; ks++) {
            uint32_t ah[2][4], al[2][4];
#pragma unroll
            for (int mi = 0; mi < 2; mi++) {
                int hoff = (wm + mi * 16 + a_row) * LDH + ks * 16 + a_kh;
                ldm_x4(ah[mi], sb + 2 * (SM_AHI + hoff));
                ldm_x4(al[mi], sb + 2 * (SM_ALO + hoff));
            }
#pragma unroll
            for (int ni = 0; ni < 8; ni++) {
                uint32_t bh[2], bl[2];
                int hoff = (wn + ni * 8 + b_row) * LDH + ks * 16 + b_kh;
                ldm_x2(bh, sb + 2 * (SM_BHI + hoff));
                ldm_x2(bl, sb + 2 * (SM_BLO + hoff));
#pragma unroll
                for (int mi = 0; mi < 2; mi++) {
                    mma_bf16(c[mi][ni], ah[mi], bh);
                    mma_bf16(c[mi][ni], al[mi], bh);
                    mma_bf16(c[mi][ni], ah[mi], bl);
                }
            }
        }
    }

    // --- epilogue: write fp16 H ---
    const int r0 = (lane >> 2);
    const int cb = (lane & 3) * 2;
#pragma unroll
    for (int mi = 0; mi < 2; mi++) {
#pragma unroll
        for (int ni = 0; ni < 8; ni++) {
            int col = wn + ni * 8 + cb;
            int gm0 = block_row + wm + mi * 16 + r0;
            int gm1 = gm0 + 8;
            if (gm0 < NN)
                *reinterpret_cast<__half2*>(g_Hh + (size_t)gm0 * OUTC + col) =
                    __floats2half2_rn(c[mi][ni][0], c[mi][ni][1]);
            if (gm1 < NN)
                *reinterpret_cast<__half2*>(g_Hh + (size_t)gm1 * OUTC + col) =
                    __floats2half2_rn(c[mi][ni][2], c[mi][ni][3]);
        }
    }
}

// ------------------------- Kernel 2: CSR row pointers (A_rows sorted) -------------------------
__global__ void row_ptr_kernel(const int* __restrict__ A_rows)
{
    int r = blockIdx.x * blockDim.x + threadIdx.x;
    if (r > NN) return;
    int lo = 0, hi = EE;
    while (lo < hi) {
        int mid = (lo + hi) >> 1;
        if (A_rows[mid] < r) lo = mid + 1;
        else                 hi = mid;
    }
    g_row_ptr[r] = lo;
}

// ------------------------- Kernel 3: CSR SpMM (fp16 H gather) -------------------------
// 128 threads = 2 rows x 64 channel-pairs. Coalesced 256B/edge gathers.
__global__ __launch_bounds__(128)
void spmm_kernel(const int*   __restrict__ A_cols,
                 const float* __restrict__ A_vals,
                 float*       __restrict__ out)
{
    const int sub = threadIdx.x >> 6;          // 0 or 1
    const int c2  = threadIdx.x & 63;          // channel pair
    const int r   = blockIdx.x * 2 + sub;
    if (r >= NN) return;

    const int beg = g_row_ptr[r];
    const int end = g_row_ptr[r + 1];

    float2 acc = make_float2(0.f, 0.f);
    for (int e = beg; e < end; e++) {
        int   col = __ldg(A_cols + e);
        float v   = __ldg(A_vals + e);
        __half2 h = *reinterpret_cast<const __half2*>(
                        g_Hh + (size_t)col * OUTC + 2 * c2);
        float2 f = __half22float2(h);
        acc.x = fmaf(v, f.x, acc.x);
        acc.y = fmaf(v, f.y, acc.y);
    }
    *reinterpret_cast<float2*>(out + (size_t)r * OUTC + 2 * c2) = acc;
}

// ---------------------------------------------------------------------------
extern "C" void kernel_launch(void* const* d_in, const int* in_sizes, int n_in,
                              void* d_out, int out_size)
{
    const float* X      = (const float*)d_in[0];   // [NN, INC]
    const float* W      = (const float*)d_in[1];   // [OUTC, INC]
    const int*   A_rows = (const int*)  d_in[2];   // [EE] sorted
    const int*   A_cols = (const int*)  d_in[3];   // [EE]
    const float* A_vals = (const float*)d_in[4];   // [EE]
    float*       out    = (float*)d_out;           // [NN, OUTC]

    cudaFuncSetAttribute(gemm_tc_kernel,
                         cudaFuncAttributeMaxDynamicSharedMemorySize, SM_BYTES);

    wconv_kernel<<<(OUTC * INC + 255) / 256, 256>>>(W);
    gemm_tc_kernel<<<(NN + 127) / 128, 256, SM_BYTES>>>(X);
    row_ptr_kernel<<<(NN + 1 + 255) / 256, 256>>>(A_rows);
    spmm_kernel<<<(NN + 1) / 2, 128>>>(A_cols, A_vals, out);
}

// round 8
// speedup vs baseline: 1.0714x; 1.0714x over previous
#include <cuda_runtime.h>
#include <cuda_bf16.h>
#include <cuda_fp16.h>
#include <cstdint>

#define NN    100000
#define EE    1600000
#define INC   256
#define OUTC  128

// ------------------------- device scratch -------------------------
__device__ __half        g_Hh[(size_t)NN * OUTC];    // H = X @ W^T (fp16)
__device__ int           g_row_ptr[NN + 1];
__device__ __nv_bfloat16 g_Whi[OUTC * INC];
__device__ __nv_bfloat16 g_Wlo[OUTC * INC];

// ------------------------- helpers -------------------------
__device__ __forceinline__ uint32_t smem_u32(const void* p) {
    uint32_t a;
    asm("{ .reg .u64 t; cvta.to.shared.u64 t, %1; cvt.u32.u64 %0, t; }"
        : "=r"(a) : "l"(p));
    return a;
}

__device__ __forceinline__ void ldm_x4(uint32_t* r, uint32_t addr) {
    asm volatile("ldmatrix.sync.aligned.m8n8.x4.shared.b16 {%0,%1,%2,%3}, [%4];"
                 : "=r"(r[0]), "=r"(r[1]), "=r"(r[2]), "=r"(r[3]) : "r"(addr));
}
__device__ __forceinline__ void ldm_x2(uint32_t* r, uint32_t addr) {
    asm volatile("ldmatrix.sync.aligned.m8n8.x2.shared.b16 {%0,%1}, [%2];"
                 : "=r"(r[0]), "=r"(r[1]) : "r"(addr));
}
__device__ __forceinline__ void mma_bf16(float* c, const uint32_t* a, const uint32_t* b) {
    asm volatile(
        "mma.sync.aligned.m16n8k16.row.col.f32.bf16.bf16.f32 "
        "{%0,%1,%2,%3}, {%4,%5,%6,%7}, {%8,%9}, {%0,%1,%2,%3};"
        : "+f"(c[0]), "+f"(c[1]), "+f"(c[2]), "+f"(c[3])
        : "r"(a[0]), "r"(a[1]), "r"(a[2]), "r"(a[3]), "r"(b[0]), "r"(b[1]));
}

// ------------------------- Kernel 0: split W into bf16 hi/lo -------------------------
__global__ void wconv_kernel(const float* __restrict__ W) {
    int i = blockIdx.x * blockDim.x + threadIdx.x;
    if (i < OUTC * INC) {
        float w = W[i];
        __nv_bfloat16 h = __float2bfloat16(w);
        float r = w - __bfloat162float(h);
        g_Whi[i] = h;
        g_Wlo[i] = __float2bfloat16(r);
    }
}

// ------------------------- Kernel 1: mma.sync bf16 split GEMM -------------------------
// H[m][n] = sum_k X[m][k] * W[n][k].  CTA tile 128x128, K-tiles of 64.
// 8 warps: warp_m = wid%4 (32 rows), warp_n = wid/4 (64 cols).
// 3 products per fragment: hi*hi + hi*lo + lo*hi.
#define LDH 72
#define SM_AHI 0
#define SM_ALO (128 * LDH)
#define SM_BHI (2 * 128 * LDH)
#define SM_BLO (3 * 128 * LDH)
#define SM_HALVES (4 * 128 * LDH)
#define SM_BYTES (SM_HALVES * 2)   // 73728

__global__ __launch_bounds__(256, 2)
void gemm_tc_kernel(const float* __restrict__ X)
{
    extern __shared__ __half sm[];
    const uint32_t sb = smem_u32(sm);

    const int tid = threadIdx.x;
    const int wid = tid >> 5;
    const int lane = tid & 31;
    const int block_row = blockIdx.x * 128;

    const int wm = (wid & 3) * 32;   // warp row offset in tile
    const int wn = (wid >> 2) * 64;  // warp col offset in tile

    float c[2][8][4];
#pragma unroll
    for (int mi = 0; mi < 2; mi++)
#pragma unroll
        for (int ni = 0; ni < 8; ni++)
#pragma unroll
            for (int j = 0; j < 4; j++)
                c[mi][ni][j] = 0.0f;

    const int a_row = (lane & 7) + 8 * ((lane >> 3) & 1);
    const int a_kh  = 8 * (lane >> 4);
    const int l2    = lane & 15;
    const int b_row = l2 & 7;
    const int b_kh  = 8 * (l2 >> 3);

#pragma unroll 1
    for (int kt = 0; kt < 4; kt++) {
        const int k0 = kt * 64;
        if (kt) __syncthreads();

        // --- X tile: 128 rows x 64 floats -> bf16 hi/lo ---
#pragma unroll
        for (int i = 0; i < 8; i++) {
            int slot = i * 256 + tid;
            int row  = slot >> 4;
            int kq   = (slot & 15) << 2;
            int gm   = block_row + row;
            float4 v = make_float4(0.f, 0.f, 0.f, 0.f);
            if (gm < NN)
                v = *reinterpret_cast<const float4*>(X + (size_t)gm * INC + k0 + kq);
            __nv_bfloat16 h0 = __float2bfloat16(v.x);
            __nv_bfloat16 h1 = __float2bfloat16(v.y);
            __nv_bfloat16 h2 = __float2bfloat16(v.z);
            __nv_bfloat16 h3 = __float2bfloat16(v.w);
            __nv_bfloat162 hp0(h0, h1), hp1(h2, h3);
            __nv_bfloat162 lp0(__float2bfloat16(v.x - __bfloat162float(h0)),
                               __float2bfloat16(v.y - __bfloat162float(h1)));
            __nv_bfloat162 lp1(__float2bfloat16(v.z - __bfloat162float(h2)),
                               __float2bfloat16(v.w - __bfloat162float(h3)));
            uint2 hw, lw;
            hw.x = *reinterpret_cast<uint32_t*>(&hp0);
            hw.y = *reinterpret_cast<uint32_t*>(&hp1);
            lw.x = *reinterpret_cast<uint32_t*>(&lp0);
            lw.y = *reinterpret_cast<uint32_t*>(&lp1);
            int off = row * LDH + kq;
            *reinterpret_cast<uint2*>(&sm[SM_AHI + off]) = hw;
            *reinterpret_cast<uint2*>(&sm[SM_ALO + off]) = lw;
        }
        // --- W tile: 128 n x 64 halves (preconverted bf16) ---
#pragma unroll
        for (int i = 0; i < 4; i++) {
            int slot = i * 256 + tid;
            int n    = slot >> 3;
            int kc   = (slot & 7) << 3;
            int off  = n * LDH + kc;
            *reinterpret_cast<uint4*>(&sm[SM_BHI + off]) =
                *reinterpret_cast<const uint4*>(g_Whi + n * INC + k0 + kc);
            *reinterpret_cast<uint4*>(&sm[SM_BLO + off]) =
                *reinterpret_cast<const uint4*>(g_Wlo + n * INC + k0 + kc);
        }
        __syncthreads();

        // --- compute: 4 k16 steps ---
#pragma unroll
        for (int ks = 0; ks < 4; ks++) {
            uint32_t ah[2][4], al[2][4];
#pragma unroll
            for (int mi = 0; mi < 2; mi++) {
                int hoff = (wm + mi * 16 + a_row) * LDH + ks * 16 + a_kh;
                ldm_x4(ah[mi], sb + 2 * (SM_AHI + hoff));
                ldm_x4(al[mi], sb + 2 * (SM_ALO + hoff));
            }
#pragma unroll
            for (int ni = 0; ni < 8; ni++) {
                uint32_t bh[2], bl[2];
                int hoff = (wn + ni * 8 + b_row) * LDH + ks * 16 + b_kh;
                ldm_x2(bh, sb + 2 * (SM_BHI + hoff));
                ldm_x2(bl, sb + 2 * (SM_BLO + hoff));
#pragma unroll
                for (int mi = 0; mi < 2; mi++) {
                    mma_bf16(c[mi][ni], ah[mi], bh);
                    mma_bf16(c[mi][ni], al[mi], bh);
                    mma_bf16(c[mi][ni], ah[mi], bl);
                }
            }
        }
    }

    // --- epilogue: write fp16 H ---
    const int r0 = (lane >> 2);
    const int cb = (lane & 3) * 2;
#pragma unroll
    for (int mi = 0; mi < 2; mi++) {
#pragma unroll
        for (int ni = 0; ni < 8; ni++) {
            int col = wn + ni * 8 + cb;
            int gm0 = block_row + wm + mi * 16 + r0;
            int gm1 = gm0 + 8;
            if (gm0 < NN)
                *reinterpret_cast<__half2*>(g_Hh + (size_t)gm0 * OUTC + col) =
                    __floats2half2_rn(c[mi][ni][0], c[mi][ni][1]);
            if (gm1 < NN)
                *reinterpret_cast<__half2*>(g_Hh + (size_t)gm1 * OUTC + col) =
                    __floats2half2_rn(c[mi][ni][2], c[mi][ni][3]);
        }
    }
}

// ------------------------- Kernel 2: CSR row pointers (A_rows sorted) -------------------------
__global__ void row_ptr_kernel(const int* __restrict__ A_rows)
{
    int r = blockIdx.x * blockDim.x + threadIdx.x;
    if (r > NN) return;
    int lo = 0, hi = EE;
    while (lo < hi) {
        int mid = (lo + hi) >> 1;
        if (A_rows[mid] < r) lo = mid + 1;
        else                 hi = mid;
    }
    g_row_ptr[r] = lo;
}

// ------------------------- Kernel 3: CSR SpMM, warp per row -------------------------
// Each warp handles one output row. Lane owns 4 channels (uint2 = 8B of fp16 H).
// Edge metadata loaded 32-at-a-time per warp and distributed via shuffles:
// per edge cost = 2 shfl + 1 LDG.64 gather (2 coalesced 128B lines) + 4 cvt/fma.
__global__ __launch_bounds__(256)
void spmm_kernel(const int*   __restrict__ A_cols,
                 const float* __restrict__ A_vals,
                 float*       __restrict__ out)
{
    const int lane = threadIdx.x & 31;
    const int r    = blockIdx.x * 8 + (threadIdx.x >> 5);
    if (r >= NN) return;                       // warp-uniform

    const int beg = g_row_ptr[r];
    const int end = g_row_ptr[r + 1];

    float4 acc = make_float4(0.f, 0.f, 0.f, 0.f);
    const __half* __restrict__ Hbase = g_Hh;

#pragma unroll 1
    for (int base = beg; base < end; base += 32) {
        int   e   = base + lane;
        int   col = 0;
        float v   = 0.f;
        if (e < end) { col = __ldg(A_cols + e); v = __ldg(A_vals + e); }
        const int cnt = min(32, end - base);

#pragma unroll 4
        for (int j = 0; j < cnt; j++) {
            int   cj = __shfl_sync(0xffffffffu, col, j);
            float vj = __shfl_sync(0xffffffffu, v,   j);
            uint2 hraw = *reinterpret_cast<const uint2*>(
                             Hbase + (size_t)cj * OUTC + lane * 4);
            __half2 h0 = *reinterpret_cast<__half2*>(&hraw.x);
            __half2 h1 = *reinterpret_cast<__half2*>(&hraw.y);
            float2 f0 = __half22float2(h0);
            float2 f1 = __half22float2(h1);
            acc.x = fmaf(vj, f0.x, acc.x);
            acc.y = fmaf(vj, f0.y, acc.y);
            acc.z = fmaf(vj, f1.x, acc.z);
            acc.w = fmaf(vj, f1.y, acc.w);
        }
    }

    *reinterpret_cast<float4*>(out + (size_t)r * OUTC + lane * 4) = acc;
}

// ---------------------------------------------------------------------------
extern "C" void kernel_launch(void* const* d_in, const int* in_sizes, int n_in,
                              void* d_out, int out_size)
{
    const float* X      = (const float*)d_in[0];   // [NN, INC]
    const float* W      = (const float*)d_in[1];   // [OUTC, INC]
    const int*   A_rows = (const int*)  d_in[2];   // [EE] sorted
    const int*   A_cols = (const int*)  d_in[3];   // [EE]
    const float* A_vals = (const float*)d_in[4];   // [EE]
    float*       out    = (float*)d_out;           // [NN, OUTC]

    cudaFuncSetAttribute(gemm_tc_kernel,
                         cudaFuncAttributeMaxDynamicSharedMemorySize, SM_BYTES);

    wconv_kernel<<<(OUTC * INC + 255) / 256, 256>>>(W);
    gemm_tc_kernel<<<(NN + 127) / 128, 256, SM_BYTES>>>(X);
    row_ptr_kernel<<<(NN + 1 + 255) / 256, 256>>>(A_rows);
    spmm_kernel<<<(NN + 7) / 8, 256>>>(A_cols, A_vals, out);
}